// round 17
// baseline (speedup 1.0000x reference)
#include <cuda_runtime.h>
#include <cuda_bf16.h>
#include <cstdint>

#define NN 4096
#define DD 64
#define NBLK 128   // 128 blocks x 32 warps = 4096 warps (co-resident on 148 SMs)

// Scratch (device globals — no allocation allowed)
__device__ float g_cost[(size_t)NN * NN];            // 64 MB
__device__ float g_costT[(size_t)NN * NN];           // 64 MB (transpose)
__device__ float g_x2[NN];
__device__ float g_y2[NN];
__device__ unsigned long long g_rowmin[NN];
__device__ unsigned long long g_colmin[NN];
__device__ unsigned long long g_rowseg[(size_t)NN * 64];  // per-row 64-col segment min
__device__ unsigned long long g_colseg[(size_t)NN * 64];  // per-col 64-row segment min
__device__ unsigned short g_scol[NN];                // row -> cached argmin col (init only)
__device__ unsigned short g_crow[NN];                // col -> cached argmin row (live)
__device__ unsigned int g_rowfreeG[NN / 32];
__device__ unsigned int g_colfreeG[NN / 32];

__device__ __forceinline__ unsigned long long umin64(unsigned long long a, unsigned long long b) {
    return a < b ? a : b;
}
__device__ __forceinline__ unsigned long long mkkey(float v, int idx) {
    return ((unsigned long long)__float_as_uint(v) << 32) | (unsigned)idx;
}

// -------------------------------------------------------------------------
// Kernel 1: squared norms + re-init of atomicMin accumulators + out prefill.
// -------------------------------------------------------------------------
__global__ void norms_kernel(const float* __restrict__ x, const float* __restrict__ y,
                             float* __restrict__ out) {
    int gt = blockIdx.x * blockDim.x + threadIdx.x;
    if (gt < NN) {
        out[gt] = (float)gt;
        g_rowmin[gt] = ~0ull;
        g_colmin[gt] = ~0ull;
    }

    int w = gt >> 5;
    int lane = gt & 31;
    if (w >= NN) return;

    float2 xv = ((const float2*)(x + w * DD))[lane];
    float p = __fadd_rn(__fmul_rn(xv.x, xv.x), __fmul_rn(xv.y, xv.y));
    #pragma unroll
    for (int o = 16; o; o >>= 1)
        p = __fadd_rn(p, __shfl_down_sync(0xFFFFFFFFu, p, o));
    if (lane == 0) g_x2[w] = p;

    float2 yv = ((const float2*)(y + w * DD))[lane];
    p = __fadd_rn(__fmul_rn(yv.x, yv.x), __fmul_rn(yv.y, yv.y));
    #pragma unroll
    for (int o = 16; o; o >>= 1)
        p = __fadd_rn(p, __shfl_down_sync(0xFFFFFFFFu, p, o));
    if (lane == 0) g_y2[w] = p;
}

// -------------------------------------------------------------------------
// Kernel 2: SGEMM-tiled cost build (validated bit-exact), fused cost+costT
// writes, per-row/col global argmins, and 64-wide SEGMENT minima.
// -------------------------------------------------------------------------
#define TSTR 68

__global__ __launch_bounds__(256)
void cost_kernel(const float* __restrict__ x, const float* __restrict__ y) {
    __shared__ __align__(16) float xsh[DD * TSTR];
    __shared__ __align__(16) float ysh[DD * TSTR];
    __shared__ unsigned long long srmin[64], scmin[64];

    int i0 = blockIdx.y * 64, j0 = blockIdx.x * 64;
    int tid = threadIdx.x;
    int tx = tid & 15, ty = tid >> 4;

    if (tid < 64) srmin[tid] = ~0ull;
    else if (tid < 128) scmin[tid - 64] = ~0ull;

    {
        int r = tid >> 2, k0 = (tid & 3) * 16;
        const float4* px = (const float4*)(x + (size_t)(i0 + r) * DD + k0);
        const float4* py = (const float4*)(y + (size_t)(j0 + r) * DD + k0);
        #pragma unroll
        for (int q = 0; q < 4; q++) {
            float4 v = px[q];
            xsh[(k0 + q * 4 + 0) * TSTR + r] = v.x;
            xsh[(k0 + q * 4 + 1) * TSTR + r] = v.y;
            xsh[(k0 + q * 4 + 2) * TSTR + r] = v.z;
            xsh[(k0 + q * 4 + 3) * TSTR + r] = v.w;
            float4 u = py[q];
            ysh[(k0 + q * 4 + 0) * TSTR + r] = u.x;
            ysh[(k0 + q * 4 + 1) * TSTR + r] = u.y;
            ysh[(k0 + q * 4 + 2) * TSTR + r] = u.z;
            ysh[(k0 + q * 4 + 3) * TSTR + r] = u.w;
        }
    }
    __syncthreads();

    float acc[4][4];
    #pragma unroll
    for (int a = 0; a < 4; a++)
        #pragma unroll
        for (int b = 0; b < 4; b++) acc[a][b] = 0.0f;

    #pragma unroll
    for (int k = 0; k < DD; k++) {
        float4 xv = *(const float4*)&xsh[k * TSTR + ty * 4];
        float4 yv = *(const float4*)&ysh[k * TSTR + tx * 4];
        float xa[4] = {xv.x, xv.y, xv.z, xv.w};
        float ya[4] = {yv.x, yv.y, yv.z, yv.w};
        #pragma unroll
        for (int a = 0; a < 4; a++)
            #pragma unroll
            for (int b = 0; b < 4; b++)
                acc[a][b] = __fmaf_rn(xa[a], ya[b], acc[a][b]);
    }

    float x2v[4], y2v[4];
    #pragma unroll
    for (int a = 0; a < 4; a++) {
        x2v[a] = g_x2[i0 + ty * 4 + a];
        y2v[a] = g_y2[j0 + tx * 4 + a];
    }
    #pragma unroll
    for (int a = 0; a < 4; a++)
        #pragma unroll
        for (int b = 0; b < 4; b++) {
            float ssum = __fadd_rn(x2v[a], y2v[b]);
            float u    = __fsub_rn(ssum, __fmul_rn(2.0f, acc[a][b]));
            float sq   = fmaxf(u, 0.0f);
            acc[a][b]  = __fsqrt_rn(sq);
        }

    #pragma unroll
    for (int a = 0; a < 4; a++) {
        unsigned long long rk = ~0ull;
        #pragma unroll
        for (int b = 0; b < 4; b++)
            rk = umin64(rk, mkkey(acc[a][b], j0 + tx * 4 + b));
        atomicMin(&srmin[ty * 4 + a], rk);
    }
    #pragma unroll
    for (int b = 0; b < 4; b++) {
        unsigned long long ck = ~0ull;
        #pragma unroll
        for (int a = 0; a < 4; a++)
            ck = umin64(ck, mkkey(acc[a][b], i0 + ty * 4 + a));
        atomicMin(&scmin[tx * 4 + b], ck);
    }

    #pragma unroll
    for (int a = 0; a < 4; a++) {
        float4 o = make_float4(acc[a][0], acc[a][1], acc[a][2], acc[a][3]);
        *(float4*)&g_cost[(size_t)(i0 + ty * 4 + a) * NN + j0 + tx * 4] = o;
    }

    __syncthreads();
    #pragma unroll
    for (int a = 0; a < 4; a++)
        #pragma unroll
        for (int b = 0; b < 4; b++)
            xsh[(tx * 4 + b) * TSTR + ty * 4 + a] = acc[a][b];
    __syncthreads();

    {
        int c = tid >> 2, k0 = (tid & 3) * 16;
        #pragma unroll
        for (int q = 0; q < 4; q++) {
            float4 v = *(const float4*)&xsh[c * TSTR + k0 + q * 4];
            *(float4*)&g_costT[(size_t)(j0 + c) * NN + i0 + k0 + q * 4] = v;
        }
    }

    if (tid < 64) {
        g_rowseg[(size_t)(i0 + tid) * 64 + blockIdx.x] = srmin[tid];
        atomicMin(&g_rowmin[i0 + tid], srmin[tid]);
    } else if (tid < 128) {
        int c = tid - 64;
        g_colseg[(size_t)(j0 + c) * 64 + blockIdx.y] = scmin[c];
        atomicMin(&g_colmin[j0 + c], scmin[c]);
    }
}

// -------------------------------------------------------------------------
// Kernel 3: init match state (every replay).
// -------------------------------------------------------------------------
__global__ void init_kernel() {
    int i = blockIdx.x * blockDim.x + threadIdx.x;
    if (i < NN) {
        g_scol[i] = (unsigned short)(g_rowmin[i] & 0xFFFFu);
        g_crow[i] = (unsigned short)(g_colmin[i] & 0xFFFFu);
    }
    if (i < NN / 32) { g_rowfreeG[i] = ~0u; g_colfreeG[i] = ~0u; }
}

// -------------------------------------------------------------------------
// Kernel 4: ASYNC matcher (validated round 15) with batched poll probes:
// all 4 cross-warp probes issued independently at loop top -> one L2
// round-trip per poll iteration instead of ~4 serialized ones.
// Protocol unchanged: warp gw owns row gw + col gw; commit = claim col bit
// via atomicAnd (linearization point); crow[j] stable while pointee free;
// pointers are superset-argmins -> exact sorted-greedy result.
// -------------------------------------------------------------------------
__global__ __launch_bounds__(1024, 1)
void pmatch_kernel(float* __restrict__ out) {
    __shared__ __align__(16) unsigned long long wseg[32][128];  // 32 KB, warp-private

    const int lane = threadIdx.x & 31, w = threadIdx.x >> 5;
    const int gw = blockIdx.x * 32 + w;

    volatile unsigned int* vcf = (volatile unsigned int*)g_colfreeG;
    volatile unsigned int* vrf = (volatile unsigned int*)g_rowfreeG;
    volatile unsigned short* vcrow = (volatile unsigned short*)g_crow;

    #pragma unroll
    for (int q = 0; q < 2; q++) {
        wseg[w][q * 32 + lane]      = g_rowseg[(size_t)gw * 64 + q * 32 + lane];
        wseg[w][64 + q * 32 + lane] = g_colseg[(size_t)gw * 64 + q * 32 + lane];
    }
    int scolReg = g_scol[gw];
    int crowReg = g_crow[gw];
    bool rowDone = false, colDone = false;

    while (true) {
        bool didWork = false;

        // ---- batched independent probes (single L2 round trip) ----
        int jj = scolReg, r2 = crowReg;
        unsigned cw_j   = vcf[jj >> 5];      // row target col alive?
        int      cr_j   = (int)vcrow[jj];    // mutual pointer?
        unsigned cw_own = vcf[gw >> 5];      // own col alive?
        unsigned rw_t   = vrf[r2 >> 5];      // col target row alive?

        // ---------------- row side (we exclusively own row gw) -----------
        if (!rowDone) {
            if (!((cw_j >> (jj & 31)) & 1)) {
                // pointer dead -> rescan row over seg hierarchy
                unsigned long long best = ~0ull;
                const float* base = g_cost + (size_t)gw * NN;
                #pragma unroll
                for (int s0 = 0; s0 < 2; s0++) {
                    int s = s0 * 32 + lane;
                    unsigned long long k = wseg[w][s];
                    if (k != ~0ull) {
                        int c = (int)(k & 0xFFFFu);
                        if (!((vcf[c >> 5] >> (c & 31)) & 1)) {
                            unsigned long long nk = ~0ull;
                            unsigned b0 = vcf[s * 2], b1 = vcf[s * 2 + 1];
                            if (b0 | b1) {
                                const float4* p = (const float4*)(base + s * 64);
                                #pragma unroll
                                for (int q = 0; q < 16; q++) {
                                    unsigned mm = ((q < 8 ? b0 : b1) >> ((q & 7) * 4)) & 0xFu;
                                    if (mm) {
                                        float4 v = p[q];
                                        if (mm & 1) nk = umin64(nk, mkkey(v.x, s * 64 + q * 4 + 0));
                                        if (mm & 2) nk = umin64(nk, mkkey(v.y, s * 64 + q * 4 + 1));
                                        if (mm & 4) nk = umin64(nk, mkkey(v.z, s * 64 + q * 4 + 2));
                                        if (mm & 8) nk = umin64(nk, mkkey(v.w, s * 64 + q * 4 + 3));
                                    }
                                }
                            }
                            wseg[w][s] = nk;
                            k = nk;
                        }
                    }
                    best = umin64(best, k);
                }
                #pragma unroll
                for (int o = 16; o; o >>= 1)
                    best = umin64(best, __shfl_down_sync(0xFFFFFFFFu, best, o));
                scolReg = (int)(__shfl_sync(0xFFFFFFFFu, best, 0) & 0xFFFFu);
                didWork = true;
            } else if (cr_j == gw) {
                unsigned old = 0;
                if (lane == 0)
                    old = atomicAnd(&g_colfreeG[jj >> 5], ~(1u << (jj & 31)));
                old = __shfl_sync(0xFFFFFFFFu, old, 0);
                if ((old >> (jj & 31)) & 1) {
                    if (lane == 0) {
                        out[gw] = (float)jj;
                        atomicAnd(&g_rowfreeG[gw >> 5], ~(1u << (gw & 31)));
                    }
                    rowDone = true;
                    didWork = true;
                }
                // claim failed -> col died; next iteration sees it and rescans
            }
        }

        // ---------------- col side (we maintain crow[gw]) ----------------
        if (!colDone) {
            if (!((cw_own >> (gw & 31)) & 1)) {
                colDone = true;
            } else if (!((rw_t >> (r2 & 31)) & 1)) {
                unsigned long long best = ~0ull;
                const float* base = g_costT + (size_t)gw * NN;
                #pragma unroll
                for (int s0 = 0; s0 < 2; s0++) {
                    int s = s0 * 32 + lane;
                    unsigned long long k = wseg[w][64 + s];
                    if (k != ~0ull) {
                        int c = (int)(k & 0xFFFFu);
                        if (!((vrf[c >> 5] >> (c & 31)) & 1)) {
                            unsigned long long nk = ~0ull;
                            unsigned b0 = vrf[s * 2], b1 = vrf[s * 2 + 1];
                            if (b0 | b1) {
                                const float4* p = (const float4*)(base + s * 64);
                                #pragma unroll
                                for (int q = 0; q < 16; q++) {
                                    unsigned mm = ((q < 8 ? b0 : b1) >> ((q & 7) * 4)) & 0xFu;
                                    if (mm) {
                                        float4 v = p[q];
                                        if (mm & 1) nk = umin64(nk, mkkey(v.x, s * 64 + q * 4 + 0));
                                        if (mm & 2) nk = umin64(nk, mkkey(v.y, s * 64 + q * 4 + 1));
                                        if (mm & 4) nk = umin64(nk, mkkey(v.z, s * 64 + q * 4 + 2));
                                        if (mm & 8) nk = umin64(nk, mkkey(v.w, s * 64 + q * 4 + 3));
                                    }
                                }
                            }
                            wseg[w][64 + s] = nk;
                            k = nk;
                        }
                    }
                    best = umin64(best, k);
                }
                #pragma unroll
                for (int o = 16; o; o >>= 1)
                    best = umin64(best, __shfl_down_sync(0xFFFFFFFFu, best, o));
                crowReg = (int)(__shfl_sync(0xFFFFFFFFu, best, 0) & 0xFFFFu);
                if (lane == 0)
                    vcrow[gw] = (unsigned short)crowReg;   // volatile store -> L2 visible
                didWork = true;
            }
        }

        if (rowDone && colDone) break;
        if (!didWork) __nanosleep(64);
    }
}

extern "C" void kernel_launch(void* const* d_in, const int* in_sizes, int n_in,
                              void* d_out, int out_size) {
    const float* x = (const float*)d_in[0];
    const float* y = (const float*)d_in[1];
    float* out = (float*)d_out;

    norms_kernel<<<512, 256>>>(x, y, out);
    cost_kernel<<<dim3(64, 64), 256>>>(x, y);
    init_kernel<<<4, 1024>>>();
    pmatch_kernel<<<NBLK, 1024>>>(out);
}